// round 14
// baseline (speedup 1.0000x reference)
#include <cuda_runtime.h>
#include <cstdint>

#define NB   64      // B
#define NP   2048    // P
#define NL   512     // L
#define NDM  512     // D_MODEL
#define NH   8       // heads
#define NDK  64
#define SPLIT 2
#define ROWS_PER_BLK (NP/SPLIT)    // 1024
#define TILE 32
#define NTILES (ROWS_PER_BLK/TILE) // 32
#define NSTG 3
#define SCSTR 33     // sc_s padded row stride
#define TILE_BYTES (TILE*NL*4)     // 65536

// float offsets inside dynamic smem of k2
#define OFF_UG    (NSTG*TILE*NL)                 // 49152
#define OFF_SC    (OFF_UG + NH*NL)               // 53248
#define OFF_EA    (OFF_SC + NH*SCSTR)            // 53512
#define OFF_SCALE (OFF_EA + 2*NH*TILE)           // 54024
#define OFF_MROW  (OFF_SCALE + 16)               // 54040
#define OFF_RROW  (OFF_MROW + TILE)              // 54072
#define OFF_END   (OFF_RROW + TILE)              // 54104
#define MBAR_BYTE_OFF (OFF_END*4)                // 216416 (8B aligned)
#define SMEM2_BYTES   (MBAR_BYTE_OFF + 64)

#define NEG_INF (__int_as_float(0xff800000))

// ------------------------- scratch (static device memory) -------------------------
__device__ float g_Q[NB*NDM];            // Q = lnq @ W_q
__device__ float g_ug[NB*NH*NL];         // (u * lnkv_g) per (b,h,l)
__device__ float g_ugs[NB*NH];           // sum_l ug
__device__ float g_ub[NB*NH];            // sum_l u * lnkv_b
__device__ float g_scores[NB*NH*NP];     // raw scores
__device__ float g_pm[NB*SPLIT*NH];      // partial max
__device__ float g_pz[NB*SPLIT*NH];      // partial Z
__device__ float g_pt[NB*SPLIT*NH];      // partial T
__device__ float g_pa[NB*SPLIT*NH*NL];   // partial A (2 MB)
__device__ float g_res[NB*NDM];          // residual = x_trafic @ res_W + res_b

// ------------------------- helpers -------------------------
__device__ __forceinline__ uint32_t s2u(const void* p) {
    return (uint32_t)__cvta_generic_to_shared(p);
}

// named barriers: free ids 2,3 ; full ids 4,5 ; producer-internal 6 ; consumer epilogue 7
#define BAR_SYNC512(id)   asm volatile("bar.sync %0, 512;"   :: "r"(id) : "memory")
#define BAR_ARRIVE512(id) asm volatile("bar.arrive %0, 512;" :: "r"(id) : "memory")
#define BAR_PROD()        asm volatile("bar.sync 6, 256;"    ::: "memory")
#define BAR_CONS()        asm volatile("bar.sync 7, 256;"    ::: "memory")

#define MBARRIER_INIT(mbar, count) \
    asm volatile("mbarrier.init.shared.b64 [%0], %1;" :: "r"(mbar), "r"((uint32_t)(count)) : "memory")
#define MBARRIER_EXPECT_TX(mbar, bytes) \
    asm volatile("mbarrier.arrive.expect_tx.shared.b64 _, [%0], %1;" :: "r"(mbar), "r"((uint32_t)(bytes)) : "memory")

__device__ __forceinline__ void mbar_wait(uint32_t mbar, uint32_t parity) {
    asm volatile(
        "{\n\t"
        ".reg .pred P1;\n\t"
        "WAIT_LOOP_%=:\n\t"
        "mbarrier.try_wait.parity.acquire.cta.shared::cta.b64 P1, [%0], %1, 0x989680;\n\t"
        "@P1 bra.uni WAIT_DONE_%=;\n\t"
        "bra.uni WAIT_LOOP_%=;\n\t"
        "WAIT_DONE_%=:\n\t"
        "}"
        :: "r"(mbar), "r"(parity) : "memory");
}

// single-instruction bulk copy global -> shared, completion via mbarrier complete_tx
__device__ __forceinline__ void bulk_g2s(uint32_t dst_smem, const void* src,
                                         uint32_t bytes, uint32_t mbar) {
    asm volatile(
        "cp.async.bulk.shared::cluster.global.mbarrier::complete_tx::bytes [%0], [%1], %2, [%3];"
        :: "r"(dst_smem), "l"(src), "r"(bytes), "r"(mbar) : "memory");
}

// packed fp32x2 math (Blackwell; ptxas never emits these from C++)
__device__ __forceinline__ unsigned long long fma2(unsigned long long a,
                                                   unsigned long long b,
                                                   unsigned long long c) {
    unsigned long long d;
    asm("fma.rn.f32x2 %0, %1, %2, %3;" : "=l"(d) : "l"(a), "l"(b), "l"(c));
    return d;
}
__device__ __forceinline__ unsigned long long add2(unsigned long long a,
                                                   unsigned long long b) {
    unsigned long long d;
    asm("add.rn.f32x2 %0, %1, %2;" : "=l"(d) : "l"(a), "l"(b));
    return d;
}
__device__ __forceinline__ unsigned long long mul2(unsigned long long a,
                                                   unsigned long long b) {
    unsigned long long d;
    asm("mul.rn.f32x2 %0, %1, %2;" : "=l"(d) : "l"(a), "l"(b));
    return d;
}
__device__ __forceinline__ unsigned long long pack2(float lo, float hi) {
    unsigned long long d;
    asm("mov.b64 %0, {%1, %2};" : "=l"(d) : "f"(lo), "f"(hi));
    return d;
}
__device__ __forceinline__ float fold2(unsigned long long a) {
    float lo, hi;
    asm("mov.b64 {%0, %1}, %2;" : "=f"(lo), "=f"(hi) : "l"(a));
    return lo + hi;
}

// =========================================================================
// Kernel 1b: two GEMMs C[64x512] = A @ W, W-slice shared across all b.
//   type 0 (blocks 0..63):   Q   = LN(x_trafic) @ W_q   (LN fused in-block)
//   type 1 (blocks 64..127): res = x_trafic @ res_W + res_b
// Also zeroes g_ugs/g_ub (block 0).
// =========================================================================
__global__ void __launch_bounds__(512) k1b_gemm(
    const float* __restrict__ x_trafic,
    const float* __restrict__ W_q, const float* __restrict__ res_W,
    const float* __restrict__ res_b,
    const float* __restrict__ lnq_g, const float* __restrict__ lnq_b)
{
    extern __shared__ float4 sm4[];
    float4* A4 = sm4;                 // [j=128][b=64] stride 65 (padded)
    float4* W4 = sm4 + 128*65;        // [j=128][c=8]
    __shared__ float mean_s[64], r_s[64];
    const int t = threadIdx.x, lane = t & 31, wid = t >> 5;
    const int type = blockIdx.x >> 6, cg = blockIdx.x & 63;
    const int c0 = cg * 8;
    const float* W = type ? res_W : W_q;

    if (blockIdx.x == 0) { g_ugs[t] = 0.f; g_ub[t] = 0.f; }   // NB*NH == 512

    if (type == 0) {
        // LN stats: warp wid -> rows wid*4 .. wid*4+3
        const float4* X4 = (const float4*)x_trafic;
        #pragma unroll
        for (int rr = 0; rr < 4; rr++) {
            const int row = wid*4 + rr;
            float s1 = 0.f, s2v = 0.f;
            #pragma unroll
            for (int i = 0; i < 4; i++) {
                float4 v = X4[row*128 + lane + 32*i];
                s1  += v.x + v.y + v.z + v.w;
                s2v += v.x*v.x + v.y*v.y + v.z*v.z + v.w*v.w;
            }
            #pragma unroll
            for (int o = 16; o > 0; o >>= 1) {
                s1  += __shfl_xor_sync(~0u, s1, o);
                s2v += __shfl_xor_sync(~0u, s2v, o);
            }
            if (lane == 0) {
                float m = s1 * (1.f/NL);
                mean_s[row] = m;
                r_s[row] = rsqrtf(s2v * (1.f/NL) - m*m + 1e-5f);
            }
        }
        __syncthreads();
    }

    // load A (LN applied for type 0): coalesced read, scatter to [j][b] stride 65
    {
        const float4* Asrc = (const float4*)x_trafic;
        const float4* G4 = (const float4*)lnq_g;
        const float4* B4 = (const float4*)lnq_b;
        #pragma unroll
        for (int k = 0; k < 16; k++) {
            int g = t + 512*k;                     // < 8192
            int bb = g >> 7, j = g & 127;
            float4 v = Asrc[g];
            if (type == 0) {
                float m = mean_s[bb], r = r_s[bb];
                float4 gv = G4[j], bv = B4[j];
                v.x = (v.x - m)*r*gv.x + bv.x;
                v.y = (v.y - m)*r*gv.y + bv.y;
                v.z = (v.z - m)*r*gv.z + bv.z;
                v.w = (v.w - m)*r*gv.w + bv.w;
            }
            A4[j*65 + bb] = v;
        }
    }
    // load W slice [512 l][8 c], transpose to W4[j][c]
    {
        float* Wf = (float*)W4;
        #pragma unroll
        for (int k = 0; k < 2; k++) {
            int idx = t + 512*k;
            int l = idx >> 1, q = idx & 1;
            float4 w = ((const float4*)W)[l*128 + (c0 >> 2) + q];
            int jrow = (l >> 2)*8;
            int e0 = l & 3;
            Wf[(jrow + q*4 + 0)*4 + e0] = w.x;
            Wf[(jrow + q*4 + 1)*4 + e0] = w.y;
            Wf[(jrow + q*4 + 2)*4 + e0] = w.z;
            Wf[(jrow + q*4 + 3)*4 + e0] = w.w;
        }
    }
    __syncthreads();

    const int b = t >> 3, c = t & 7;
    float acc = 0.f;
    #pragma unroll 8
    for (int j = 0; j < 128; j++) {
        float4 va = A4[j*65 + b];
        float4 vw = W4[j*8 + c];
        acc += va.x*vw.x + va.y*vw.y + va.z*vw.z + va.w*vw.w;
    }
    if (type) g_res[b*NDM + c0 + c] = acc + res_b[c0 + c];
    else      g_Q  [b*NDM + c0 + c] = acc;
}

// =========================================================================
// Kernel 1c: u[b,h,l] for 4 l per block; g_ug, partial ugs/ub via atomics.
// =========================================================================
__global__ void __launch_bounds__(512) k1c_u(
    const float* __restrict__ W_k,
    const float* __restrict__ lnkv_g, const float* __restrict__ lnkv_b)
{
    __shared__ float4 W_s4[64*9];
    __shared__ float lkg[4], lkb[4];
    const int t = threadIdx.x;
    const int l0 = blockIdx.x * 4;

    {
        int lrow = t >> 7, dm4 = t & 127;
        float4 w = ((const float4*)W_k)[(l0 + lrow)*128 + dm4];
        W_s4[(lrow*16 + (dm4 & 15))*9 + (dm4 >> 4)] = w;
    }
    if (t < 4) { lkg[t] = lnkv_g[l0 + t]; lkb[t] = lnkv_b[l0 + t]; }
    __syncthreads();

    const int b = t >> 3, h = t & 7;
    float4 Qr[16];
    const float4* Q4 = (const float4*)g_Q;
    #pragma unroll
    for (int i = 0; i < 16; i++) Qr[i] = Q4[b*128 + h*16 + i];

    float ugs_p = 0.f, ub_p = 0.f;
    #pragma unroll
    for (int l = 0; l < 4; l++) {
        float u = 0.f;
        #pragma unroll
        for (int i = 0; i < 16; i++) {
            float4 w = W_s4[(l*16 + i)*9 + h];
            u += Qr[i].x*w.x + Qr[i].y*w.y + Qr[i].z*w.z + Qr[i].w*w.w;
        }
        float ug = u * lkg[l];
        g_ug[(b*NH + h)*NL + l0 + l] = ug;
        ugs_p += ug;
        ub_p  += u * lkb[l];
    }
    atomicAdd(&g_ugs[b*NH + h], ugs_p);
    atomicAdd(&g_ub [b*NH + h], ub_p);
}

// =========================================================================
// Kernel 2: warp-specialized producer/consumer pipeline over x_dynamic.
//  Tile loads via single-thread cp.async.bulk + mbarrier complete_tx
//  (stage-free gating provided by the ea-free named barrier).
//  producers (warps 0-7):  phase3 dots+stats, phase4 softmax
//  consumers (warps 8-15): phase5 on previous tile, pg-split
// =========================================================================
__global__ void __launch_bounds__(512, 1) k2_main(const float* __restrict__ x_dyn)
{
    extern __shared__ float sm[];
    float* buf     = sm;                 // NSTG*32*512
    float* ug_s    = sm + OFF_UG;        // 4096
    float* sc_s    = sm + OFF_SC;        // 8*33
    float* ea_s    = sm + OFF_EA;        // 2*256
    float* scale_s = sm + OFF_SCALE;     // 16
    float* mrow_s  = sm + OFF_MROW;      // 32
    float* rrow_s  = sm + OFF_RROW;      // 32

    const int t = threadIdx.x;
    const int split = blockIdx.x, b = blockIdx.y;
    const int lane = t & 31, wid = t >> 5;
    const uint32_t smem_base = s2u(sm);
    const uint32_t mb0 = smem_base + MBAR_BYTE_OFF;

    // all 512 threads load ug (4096 floats); t==0 inits mbarriers
    {
        const float4* gug4 = (const float4*)(g_ug + (size_t)b*NH*NL);
        float4* ug4 = (float4*)ug_s;
        ug4[t]       = gug4[t];
        ug4[t + 512] = gug4[t + 512];
    }
    if (t == 0) {
        MBARRIER_INIT(mb0 + 0,  1);
        MBARRIER_INIT(mb0 + 8,  1);
        MBARRIER_INIT(mb0 + 16, 1);
    }
    __syncthreads();

    const float* xbase = x_dyn + ((size_t)b*NP + (size_t)split*ROWS_PER_BLK)*NL;

    if (wid < 8) {
        // =================== PRODUCER (warps 0-7) ===================
        const float ugs_r = g_ugs[b*NH + (lane & 7)];
        const float ub_r  = g_ub [b*NH + (lane & 7)];
        float mr = NEG_INF, zr = 0.f, tr = 0.f;    // online softmax state (warp=head)
        const bool issuer = (wid == 0) && (lane == 0);

        // issue tile 0 into stage 0
        if (issuer) {
            MBARRIER_EXPECT_TX(mb0, TILE_BYTES);
            bulk_g2s(smem_base, xbase, TILE_BYTES, mb0);
        }

        int st_cur = 0, ph_cur = 0;    // stage/phase being consumed
        int st_nxt = 1, ph_nxt = 0;    // stage/phase of next issued tile
        #pragma unroll 1
        for (int tile = 0; tile < NTILES; tile++) {
            if (tile >= 2) BAR_SYNC512(2 + (tile & 1));   // consumer done tile-2 -> stage (tile+1)%3 free

            if (issuer && (tile + 1 < NTILES)) {
                MBARRIER_EXPECT_TX(mb0 + st_nxt*8, TILE_BYTES);
                bulk_g2s(smem_base + (uint32_t)st_nxt*TILE_BYTES,
                         xbase + (size_t)(tile+1)*TILE*NL, TILE_BYTES, mb0 + st_nxt*8);
            }
            mbar_wait(mb0 + st_cur*8, (uint32_t)ph_cur);  // tile data ready
            BAR_PROD();          // phase4(t-1) done by all producers; sc_s free

            // ---- phase 3: warp wid -> rows wid*4..+3, all 8 heads ----
            {
                const ulonglong2* xw2 = (const ulonglong2*)(buf + st_cur*TILE*NL) + (wid*4)*128;
                const ulonglong2* ug2 = (const ulonglong2*)ug_s;
                unsigned long long d2[4][8];
                unsigned long long s2[4], q2[4];
                #pragma unroll
                for (int r = 0; r < 4; r++) {
                    s2[r] = 0ull; q2[r] = 0ull;
                    #pragma unroll
                    for (int h = 0; h < 8; h++) d2[r][h] = 0ull;
                }
                #pragma unroll
                for (int i = 0; i < 4; i++) {
                    const int idx = lane + 32*i;
                    ulonglong2 u[8];
                    #pragma unroll
                    for (int h = 0; h < 8; h++) u[h] = ug2[h*128 + idx];
                    #pragma unroll
                    for (int r = 0; r < 4; r++) {
                        ulonglong2 v = xw2[r*128 + idx];
                        s2[r] = add2(s2[r], v.x);
                        s2[r] = add2(s2[r], v.y);
                        q2[r] = fma2(v.x, v.x, q2[r]);
                        q2[r] = fma2(v.y, v.y, q2[r]);
                        #pragma unroll
                        for (int h = 0; h < 8; h++) {
                            d2[r][h] = fma2(v.x, u[h].x, d2[r][h]);
                            d2[r][h] = fma2(v.y, u[h].y, d2[r][h]);
                        }
                    }
                }
                float dd[32], st[8];
                #pragma unroll
                for (int r = 0; r < 4; r++) {
                    st[r]   = fold2(s2[r]);
                    st[4+r] = fold2(q2[r]);
                    #pragma unroll
                    for (int h = 0; h < 8; h++) dd[r*8+h] = fold2(d2[r][h]);
                }
                // butterfly multi-value reduce: lane k ends with sum of dd[k]
                #pragma unroll
                for (int o = 16; o >= 1; o >>= 1) {
                    #pragma unroll
                    for (int i = 0; i < o; i++) {
                        bool hi = (lane & o) != 0;
                        float mine   = hi ? dd[i+o] : dd[i];
                        float theirs = hi ? dd[i]   : dd[i+o];
                        dd[i] = mine + __shfl_xor_sync(0xffffffffu, theirs, o);
                    }
                }
                // stats: lane k ends with st[k&7]
                #pragma unroll
                for (int o = 16; o >= 8; o >>= 1) {
                    #pragma unroll
                    for (int i = 0; i < 8; i++)
                        st[i] += __shfl_xor_sync(0xffffffffu, st[i], o);
                }
                #pragma unroll
                for (int o = 4; o >= 1; o >>= 1) {
                    #pragma unroll
                    for (int i = 0; i < o; i++) {
                        bool hi = (lane & o) != 0;
                        float mine   = hi ? st[i+o] : st[i];
                        float theirs = hi ? st[i]   : st[i+o];
                        st[i] = mine + __shfl_xor_sync(0xffffffffu, theirs, o);
                    }
                }

                const int r = lane >> 3, h = lane & 7;
                float sfin = st[0];
                float mean = __shfl_sync(0xffffffffu, sfin, r) * (1.f/NL);
                float sqv  = __shfl_sync(0xffffffffu, sfin, r + 4) * (1.f/NL);
                float rs   = rsqrtf(sqv - mean*mean + 1e-5f);
                float s = (rs * (dd[0] - mean * ugs_r) + ub_r) * 0.125f;
                sc_s[h*SCSTR + wid*4 + r] = s;
                if (h == 0) { mrow_s[wid*4 + r] = mean; rrow_s[wid*4 + r] = rs; }
            }
            BAR_PROD();          // sc/mrow/rrow ready

            // ---- phase 4: warp wid = head wid; softmax over 32 p ----
            {
                const int p = lane;
                float s = sc_s[wid*SCSTR + p];
                float tmax = s;
                #pragma unroll
                for (int o = 16; o > 0; o >>= 1)
                    tmax = fmaxf(tmax, __shfl_xor_sync(~0u, tmax, o));
                float mn = fmaxf(mr, tmax);
                float e  = __expf(s - mn);
                float ea = e * rrow_s[p];
                float z = e, tt = ea * mrow_s[p];
                #pragma unroll
                for (int o = 16; o > 0; o >>= 1) {
                    z  += __shfl_xor_sync(~0u, z,  o);
                    tt += __shfl_xor_sync(~0u, tt, o);
                }
                float scale = __expf(mr - mn);
                zr = zr*scale + z;
                tr = tr*scale + tt;
                mr = mn;
                ea_s[(tile & 1)*NH*TILE + wid*TILE + p] = ea;
                if (lane == 0) scale_s[(tile & 1)*NH + wid] = scale;
                g_scores[((size_t)(b*NH + wid))*NP + split*ROWS_PER_BLK + tile*TILE + p] = s;
            }
            BAR_ARRIVE512(4 + (tile & 1));   // signal ea full

            if (++st_cur == NSTG) { st_cur = 0; ph_cur ^= 1; }
            if (++st_nxt == NSTG) { st_nxt = 0; ph_nxt ^= 1; }
        }

        if (lane == 0) {
            int idx = (b*SPLIT + split)*NH + wid;
            g_pm[idx] = mr;
            g_pz[idx] = zr;
            g_pt[idx] = tr;
        }
    } else {
        // =================== CONSUMER (warps 8-15), pg-split ===================
        const int tc = t - 256;            // 0..255
        const int cg = tc & 127;           // 16B column group
        const int pg = tc >> 7;            // p half: [pg*16, pg*16+16)
        ulonglong2 A2[8];                  // A2[h] = 4 cols for head h
        #pragma unroll
        for (int j = 0; j < 8; j++) { A2[j].x = 0ull; A2[j].y = 0ull; }

        int st_cur = 0, ph_cur = 0;
        #pragma unroll 1
        for (int tile = 0; tile < NTILES; tile++) {
            BAR_SYNC512(4 + (tile & 1));                   // ea full
            mbar_wait(mb0 + st_cur*8, (uint32_t)ph_cur);   // async-proxy visibility (fast path)

            const float* eab = ea_s + (tile & 1)*NH*TILE;
            #pragma unroll
            for (int j = 0; j < 8; j++) {
                float sj = scale_s[(tile & 1)*NH + j];
                unsigned long long sj2 = pack2(sj, sj);
                A2[j].x = mul2(A2[j].x, sj2);
                A2[j].y = mul2(A2[j].y, sj2);
            }
            const ulonglong2* xc2 = (const ulonglong2*)(buf + st_cur*TILE*NL);
            #pragma unroll
            for (int pq = 0; pq < 4; pq++) {
                const int p0 = pg*16 + pq*4;
                ulonglong2 v0 = xc2[(p0+0)*128 + cg];
                ulonglong2 v1 = xc2[(p0+1)*128 + cg];
                ulonglong2 v2 = xc2[(p0+2)*128 + cg];
                ulonglong2 v3 = xc2[(p0+3)*128 + cg];
                #pragma unroll
                for (int j = 0; j < 8; j++) {
                    float4 e = *(const float4*)&eab[j*TILE + p0];
                    unsigned long long q0 = pack2(e.x, e.x);
                    unsigned long long q1 = pack2(e.y, e.y);
                    unsigned long long q2_ = pack2(e.z, e.z);
                    unsigned long long q3 = pack2(e.w, e.w);
                    A2[j].x = fma2(q0, v0.x, A2[j].x);  A2[j].y = fma2(q0, v0.y, A2[j].y);
                    A2[j].x = fma2(q1, v1.x, A2[j].x);  A2[j].y = fma2(q1, v1.y, A2[j].y);
                    A2[j].x = fma2(q2_, v2.x, A2[j].x); A2[j].y = fma2(q2_, v2.y, A2[j].y);
                    A2[j].x = fma2(q3, v3.x, A2[j].x);  A2[j].y = fma2(q3, v3.y, A2[j].y);
                }
            }
            BAR_ARRIVE512(2 + (tile & 1));   // signal ea/stage free

            if (++st_cur == NSTG) { st_cur = 0; ph_cur ^= 1; }
        }

        // epilogue: combine the two p-halves via the (now idle) staging buffer
        BAR_CONS();                          // all consumers done reading buf
        if (pg == 1) {
            float4* tmp = (float4*)buf;
            #pragma unroll
            for (int j = 0; j < 8; j++) tmp[j*128 + cg] = *(float4*)&A2[j];
        }
        BAR_CONS();
        if (pg == 0) {
            const float4* tmp = (const float4*)buf;
            float4* pa = (float4*)(g_pa + (size_t)(b*SPLIT + split)*NH*NL);
            #pragma unroll
            for (int j = 0; j < 8; j++) {
                float4 o = tmp[j*128 + cg];
                float4 a = *(float4*)&A2[j];
                o.x += a.x; o.y += a.y; o.z += a.z; o.w += a.w;
                pa[j*128 + cg] = o;
            }
        }
    }
}

// =========================================================================
// Kernel 3: combine split partials per (b,h); project through W_v;
//           write out = residual + ctx; write normalized attn row
// =========================================================================
__global__ void __launch_bounds__(256) k3_combine(
    const float* __restrict__ W_v,
    const float* __restrict__ lnkv_g, const float* __restrict__ lnkv_b,
    float* __restrict__ out)
{
    __shared__ float es[SPLIT];
    __shared__ float sT, sInvZ, sM;
    __shared__ float cvec[NL];
    __shared__ float part[4*64];

    const int t = threadIdx.x;
    const int b = blockIdx.x >> 3, h = blockIdx.x & 7;

    if (t == 0) {
        float M = NEG_INF;
        #pragma unroll
        for (int i = 0; i < SPLIT; i++)
            M = fmaxf(M, g_pm[(b*SPLIT + i)*NH + h]);
        float Z = 0.f, T = 0.f;
        #pragma unroll
        for (int i = 0; i < SPLIT; i++) {
            int idx = (b*SPLIT + i)*NH + h;
            float e = __expf(g_pm[idx] - M);
            es[i] = e;
            Z += g_pz[idx] * e;
            T += g_pt[idx] * e;
        }
        float iz = 1.f / Z;
        sT = T; sInvZ = iz; sM = M;
    }
    __syncthreads();

    for (int l = t; l < NL; l += 256) {
        float A = 0.f;
        #pragma unroll
        for (int i = 0; i < SPLIT; i++)
            A += g_pa[((size_t)(b*SPLIT + i)*NH + h)*NL + l] * es[i];
        cvec[l] = lnkv_g[l] * (A - sT) * sInvZ + lnkv_b[l];
    }
    __syncthreads();

    {
        const int d = t & 63, lg = t >> 6;
        float acc = 0.f;
        const int l0 = lg * 128;
        #pragma unroll 4
        for (int l = l0; l < l0 + 128; l++)
            acc += cvec[l] * W_v[l*NDM + h*NDK + d];
        part[lg*64 + d] = acc;
    }
    __syncthreads();
    if (t < 64) {
        float c = part[t] + part[64+t] + part[128+t] + part[192+t];
        out[b*NDM + h*NDK + t] = c + g_res[b*NDM + h*NDK + t];
    }

    // attn output row for this (b,h): exp(score - M) * invZ
    {
        const float M = sM, iz = sInvZ;
        const float4* sc4 = (const float4*)(g_scores + ((size_t)(b*NH + h))*NP);
        float4* ao = (float4*)(out + NB*NDM + ((size_t)(b*NH + h))*NP);
        #pragma unroll
        for (int j = t; j < NP/4; j += 256) {
            float4 s = sc4[j];
            float4 o;
            o.x = __expf(s.x - M) * iz;
            o.y = __expf(s.y - M) * iz;
            o.z = __expf(s.z - M) * iz;
            o.w = __expf(s.w - M) * iz;
            ao[j] = o;
        }
    }
}

// =========================================================================
extern "C" void kernel_launch(void* const* d_in, const int* in_sizes, int n_in,
                              void* d_out, int out_size)
{
    const float* x_trafic  = (const float*)d_in[0];
    const float* x_dynamic = (const float*)d_in[1];
    // d_in[2] x_known unused by the reference
    const float* W_q    = (const float*)d_in[3];
    const float* W_k    = (const float*)d_in[4];
    const float* W_v    = (const float*)d_in[5];
    const float* lnq_g  = (const float*)d_in[6];
    const float* lnq_b  = (const float*)d_in[7];
    const float* lnkv_g = (const float*)d_in[8];
    const float* lnkv_b = (const float*)d_in[9];
    const float* res_W  = (const float*)d_in[10];
    const float* res_b  = (const float*)d_in[11];
    float* out = (float*)d_out;

    const int smem1b = (128*65 + 128*8) * (int)sizeof(float4);   // ~149.5 KB
    const int smem2  = SMEM2_BYTES;                              // ~211.4 KB
    cudaFuncSetAttribute(k1b_gemm, cudaFuncAttributeMaxDynamicSharedMemorySize, smem1b);
    cudaFuncSetAttribute(k2_main,  cudaFuncAttributeMaxDynamicSharedMemorySize, smem2);

    k1b_gemm<<<128, 512, smem1b>>>(x_trafic, W_q, res_W, res_b, lnq_g, lnq_b);
    k1c_u<<<128, 512>>>(W_k, lnkv_g, lnkv_b);
    k2_main<<<dim3(SPLIT, NB), 512, smem2>>>(x_dynamic);
    k3_combine<<<NB*NH, 256>>>(W_v, lnkv_g, lnkv_b, out);
}

// round 15
// speedup vs baseline: 1.3919x; 1.3919x over previous
#include <cuda_runtime.h>
#include <cstdint>

#define NB   64      // B
#define NP   2048    // P
#define NL   512     // L
#define NDM  512     // D_MODEL
#define NH   8       // heads
#define NDK  64
#define SPLIT 2
#define ROWS_PER_BLK (NP/SPLIT)    // 1024
#define TILE 32
#define NTILES (ROWS_PER_BLK/TILE) // 32
#define NSTG 3
#define SCSTR 33     // sc_s padded row stride

#define NEG_INF (__int_as_float(0xff800000))

// ------------------------- scratch (static device memory) -------------------------
__device__ float g_Q[NB*NDM];            // Q = lnq @ W_q
__device__ float g_ug[NB*NH*NL];         // (u * lnkv_g) per (b,h,l)
__device__ float g_ugs[NB*NH];           // sum_l ug
__device__ float g_ub[NB*NH];            // sum_l u * lnkv_b
__device__ float g_scores[NB*NH*NP];     // raw scores
__device__ float g_pm[NB*SPLIT*NH];      // partial max
__device__ float g_pz[NB*SPLIT*NH];      // partial Z
__device__ float g_pt[NB*SPLIT*NH];      // partial T
__device__ float g_pa[NB*SPLIT*NH*NL];   // partial A (2 MB)
__device__ float g_res[NB*NDM];          // residual = x_trafic @ res_W + res_b

// ------------------------- helpers -------------------------
__device__ __forceinline__ uint32_t s2u(const void* p) {
    return (uint32_t)__cvta_generic_to_shared(p);
}
__device__ __forceinline__ void cp_async16(uint32_t s, const void* g) {
    asm volatile("cp.async.cg.shared.global [%0], [%1], 16;\n" :: "r"(s), "l"(g));
}
#define CP_COMMIT() asm volatile("cp.async.commit_group;\n")
#define CP_WAIT1()  asm volatile("cp.async.wait_group 1;\n")

// named barriers: free ids 2,3 ; full ids 4,5 ; producer-internal 6 ; consumer epilogue 7
#define BAR_SYNC512(id)   asm volatile("bar.sync %0, 512;"   :: "r"(id) : "memory")
#define BAR_ARRIVE512(id) asm volatile("bar.arrive %0, 512;" :: "r"(id) : "memory")
#define BAR_PROD()        asm volatile("bar.sync 6, 256;"    ::: "memory")
#define BAR_CONS()        asm volatile("bar.sync 7, 256;"    ::: "memory")

// packed fp32x2 math (Blackwell; ptxas never emits these from C++)
__device__ __forceinline__ unsigned long long fma2(unsigned long long a,
                                                   unsigned long long b,
                                                   unsigned long long c) {
    unsigned long long d;
    asm("fma.rn.f32x2 %0, %1, %2, %3;" : "=l"(d) : "l"(a), "l"(b), "l"(c));
    return d;
}
__device__ __forceinline__ unsigned long long add2(unsigned long long a,
                                                   unsigned long long b) {
    unsigned long long d;
    asm("add.rn.f32x2 %0, %1, %2;" : "=l"(d) : "l"(a), "l"(b));
    return d;
}
__device__ __forceinline__ unsigned long long mul2(unsigned long long a,
                                                   unsigned long long b) {
    unsigned long long d;
    asm("mul.rn.f32x2 %0, %1, %2;" : "=l"(d) : "l"(a), "l"(b));
    return d;
}
__device__ __forceinline__ unsigned long long pack2(float lo, float hi) {
    unsigned long long d;
    asm("mov.b64 %0, {%1, %2};" : "=l"(d) : "f"(lo), "f"(hi));
    return d;
}
__device__ __forceinline__ float fold2(unsigned long long a) {
    float lo, hi;
    asm("mov.b64 {%0, %1}, %2;" : "=f"(lo), "=f"(hi) : "l"(a));
    return lo + hi;
}

// =========================================================================
// Kernel 1b: two GEMMs C[64x512] = A @ W, W-slice shared across all b.
//   type 0 (blocks 0..63):   Q   = LN(x_trafic) @ W_q   (LN fused in-block)
//   type 1 (blocks 64..127): res = x_trafic @ res_W + res_b
// Also zeroes g_ugs/g_ub (block 0).
// =========================================================================
__global__ void __launch_bounds__(512) k1b_gemm(
    const float* __restrict__ x_trafic,
    const float* __restrict__ W_q, const float* __restrict__ res_W,
    const float* __restrict__ res_b,
    const float* __restrict__ lnq_g, const float* __restrict__ lnq_b)
{
    extern __shared__ float4 sm4[];
    float4* A4 = sm4;                 // [j=128][b=64] stride 65 (padded)
    float4* W4 = sm4 + 128*65;        // [j=128][c=8]
    __shared__ float mean_s[64], r_s[64];
    const int t = threadIdx.x, lane = t & 31, wid = t >> 5;
    const int type = blockIdx.x >> 6, cg = blockIdx.x & 63;
    const int c0 = cg * 8;
    const float* W = type ? res_W : W_q;

    if (blockIdx.x == 0) { g_ugs[t] = 0.f; g_ub[t] = 0.f; }   // NB*NH == 512

    if (type == 0) {
        // LN stats: warp wid -> rows wid*4 .. wid*4+3
        const float4* X4 = (const float4*)x_trafic;
        #pragma unroll
        for (int rr = 0; rr < 4; rr++) {
            const int row = wid*4 + rr;
            float s1 = 0.f, s2v = 0.f;
            #pragma unroll
            for (int i = 0; i < 4; i++) {
                float4 v = X4[row*128 + lane + 32*i];
                s1  += v.x + v.y + v.z + v.w;
                s2v += v.x*v.x + v.y*v.y + v.z*v.z + v.w*v.w;
            }
            #pragma unroll
            for (int o = 16; o > 0; o >>= 1) {
                s1  += __shfl_xor_sync(~0u, s1, o);
                s2v += __shfl_xor_sync(~0u, s2v, o);
            }
            if (lane == 0) {
                float m = s1 * (1.f/NL);
                mean_s[row] = m;
                r_s[row] = rsqrtf(s2v * (1.f/NL) - m*m + 1e-5f);
            }
        }
        __syncthreads();
    }

    // load A (LN applied for type 0): coalesced read, scatter to [j][b] stride 65
    {
        const float4* Asrc = (const float4*)x_trafic;
        const float4* G4 = (const float4*)lnq_g;
        const float4* B4 = (const float4*)lnq_b;
        #pragma unroll
        for (int k = 0; k < 16; k++) {
            int g = t + 512*k;                     // < 8192
            int bb = g >> 7, j = g & 127;
            float4 v = Asrc[g];
            if (type == 0) {
                float m = mean_s[bb], r = r_s[bb];
                float4 gv = G4[j], bv = B4[j];
                v.x = (v.x - m)*r*gv.x + bv.x;
                v.y = (v.y - m)*r*gv.y + bv.y;
                v.z = (v.z - m)*r*gv.z + bv.z;
                v.w = (v.w - m)*r*gv.w + bv.w;
            }
            A4[j*65 + bb] = v;
        }
    }
    // load W slice [512 l][8 c], transpose to W4[j][c]
    {
        float* Wf = (float*)W4;
        #pragma unroll
        for (int k = 0; k < 2; k++) {
            int idx = t + 512*k;
            int l = idx >> 1, q = idx & 1;
            float4 w = ((const float4*)W)[l*128 + (c0 >> 2) + q];
            int jrow = (l >> 2)*8;
            int e0 = l & 3;
            Wf[(jrow + q*4 + 0)*4 + e0] = w.x;
            Wf[(jrow + q*4 + 1)*4 + e0] = w.y;
            Wf[(jrow + q*4 + 2)*4 + e0] = w.z;
            Wf[(jrow + q*4 + 3)*4 + e0] = w.w;
        }
    }
    __syncthreads();

    const int b = t >> 3, c = t & 7;
    float acc = 0.f;
    #pragma unroll 8
    for (int j = 0; j < 128; j++) {
        float4 va = A4[j*65 + b];
        float4 vw = W4[j*8 + c];
        acc += va.x*vw.x + va.y*vw.y + va.z*vw.z + va.w*vw.w;
    }
    if (type) g_res[b*NDM + c0 + c] = acc + res_b[c0 + c];
    else      g_Q  [b*NDM + c0 + c] = acc;
}

// =========================================================================
// Kernel 1c: u[b,h,l] for 4 l per block; g_ug, partial ugs/ub via atomics.
// =========================================================================
__global__ void __launch_bounds__(512) k1c_u(
    const float* __restrict__ W_k,
    const float* __restrict__ lnkv_g, const float* __restrict__ lnkv_b)
{
    __shared__ float4 W_s4[64*9];
    __shared__ float lkg[4], lkb[4];
    const int t = threadIdx.x;
    const int l0 = blockIdx.x * 4;

    {
        int lrow = t >> 7, dm4 = t & 127;
        float4 w = ((const float4*)W_k)[(l0 + lrow)*128 + dm4];
        W_s4[(lrow*16 + (dm4 & 15))*9 + (dm4 >> 4)] = w;
    }
    if (t < 4) { lkg[t] = lnkv_g[l0 + t]; lkb[t] = lnkv_b[l0 + t]; }
    __syncthreads();

    const int b = t >> 3, h = t & 7;
    float4 Qr[16];
    const float4* Q4 = (const float4*)g_Q;
    #pragma unroll
    for (int i = 0; i < 16; i++) Qr[i] = Q4[b*128 + h*16 + i];

    float ugs_p = 0.f, ub_p = 0.f;
    #pragma unroll
    for (int l = 0; l < 4; l++) {
        float u = 0.f;
        #pragma unroll
        for (int i = 0; i < 16; i++) {
            float4 w = W_s4[(l*16 + i)*9 + h];
            u += Qr[i].x*w.x + Qr[i].y*w.y + Qr[i].z*w.z + Qr[i].w*w.w;
        }
        float ug = u * lkg[l];
        g_ug[(b*NH + h)*NL + l0 + l] = ug;
        ugs_p += ug;
        ub_p  += u * lkb[l];
    }
    atomicAdd(&g_ugs[b*NH + h], ugs_p);
    atomicAdd(&g_ub [b*NH + h], ub_p);
}

// =========================================================================
// Kernel 2 (R13-proven): warp-specialized producer/consumer pipeline.
// =========================================================================
__global__ void __launch_bounds__(512, 1) k2_main(const float* __restrict__ x_dyn)
{
    extern __shared__ float sm[];
    float* buf     = sm;                       // NSTG*32*512 = 49152
    float* ug_s    = sm + NSTG*TILE*NL;        // 4096
    float* sc_s    = ug_s + NH*NL;             // 8*33 = 264
    float* ea_s    = sc_s + NH*SCSTR;          // 2*256 = 512
    float* scale_s = ea_s + 2*NH*TILE;         // 16
    float* mrow_s  = scale_s + 16;             // 32
    float* rrow_s  = mrow_s + TILE;            // 32

    const int t = threadIdx.x;
    const int split = blockIdx.x, b = blockIdx.y;
    const int lane = t & 31, wid = t >> 5;

    // all 512 threads load ug (4096 floats)
    {
        const float4* gug4 = (const float4*)(g_ug + (size_t)b*NH*NL);
        float4* ug4 = (float4*)ug_s;
        ug4[t]       = gug4[t];
        ug4[t + 512] = gug4[t + 512];
    }
    __syncthreads();

    const float* xbase = x_dyn + ((size_t)b*NP + (size_t)split*ROWS_PER_BLK)*NL;

    if (wid < 8) {
        // =================== PRODUCER (warps 0-7) ===================
        const int tp = t;                          // 0..255
        const float ugs_r = g_ugs[b*NH + (lane & 7)];
        const float ub_r  = g_ub [b*NH + (lane & 7)];
        float mr = NEG_INF, zr = 0.f, tr = 0.f;    // online softmax state (warp=head)

        // prefetch tile 0 into stage 0
        {
            uint32_t dst = s2u(buf);
            const float4* src = (const float4*)xbase;
            #pragma unroll
            for (int j = 0; j < 16; j++)
                cp_async16(dst + (uint32_t)(tp + 256*j)*16u, src + tp + 256*j);
            CP_COMMIT();
        }

        int st_cur = 0, st_nxt = 1;
        #pragma unroll 1
        for (int tile = 0; tile < NTILES; tile++) {
            if (tile >= 2) BAR_SYNC512(2 + (tile & 1));   // consumer done tile-2

            if (tile + 1 < NTILES) {
                uint32_t dst = s2u(buf + st_nxt*TILE*NL);
                const float4* src = (const float4*)(xbase + (size_t)(tile+1)*TILE*NL);
                #pragma unroll
                for (int j = 0; j < 16; j++)
                    cp_async16(dst + (uint32_t)(tp + 256*j)*16u, src + tp + 256*j);
            }
            CP_COMMIT();
            CP_WAIT1();          // tile's data arrived (this thread)
            BAR_PROD();          // visible to all producers; sc_s free

            // ---- phase 3: warp wid -> rows wid*4..+3, all 8 heads ----
            {
                const ulonglong2* xw2 = (const ulonglong2*)(buf + st_cur*TILE*NL) + (wid*4)*128;
                const ulonglong2* ug2 = (const ulonglong2*)ug_s;
                unsigned long long d2[4][8];
                unsigned long long s2[4], q2[4];
                #pragma unroll
                for (int r = 0; r < 4; r++) {
                    s2[r] = 0ull; q2[r] = 0ull;
                    #pragma unroll
                    for (int h = 0; h < 8; h++) d2[r][h] = 0ull;
                }
                #pragma unroll
                for (int i = 0; i < 4; i++) {
                    const int idx = lane + 32*i;
                    ulonglong2 u[8];
                    #pragma unroll
                    for (int h = 0; h < 8; h++) u[h] = ug2[h*128 + idx];
                    #pragma unroll
                    for (int r = 0; r < 4; r++) {
                        ulonglong2 v = xw2[r*128 + idx];
                        s2[r] = add2(s2[r], v.x);
                        s2[r] = add2(s2[r], v.y);
                        q2[r] = fma2(v.x, v.x, q2[r]);
                        q2[r] = fma2(v.y, v.y, q2[r]);
                        #pragma unroll
                        for (int h = 0; h < 8; h++) {
                            d2[r][h] = fma2(v.x, u[h].x, d2[r][h]);
                            d2[r][h] = fma2(v.y, u[h].y, d2[r][h]);
                        }
                    }
                }
                float dd[32], st[8];
                #pragma unroll
                for (int r = 0; r < 4; r++) {
                    st[r]   = fold2(s2[r]);
                    st[4+r] = fold2(q2[r]);
                    #pragma unroll
                    for (int h = 0; h < 8; h++) dd[r*8+h] = fold2(d2[r][h]);
                }
                #pragma unroll
                for (int o = 16; o >= 1; o >>= 1) {
                    #pragma unroll
                    for (int i = 0; i < o; i++) {
                        bool hi = (lane & o) != 0;
                        float mine   = hi ? dd[i+o] : dd[i];
                        float theirs = hi ? dd[i]   : dd[i+o];
                        dd[i] = mine + __shfl_xor_sync(0xffffffffu, theirs, o);
                    }
                }
                #pragma unroll
                for (int o = 16; o >= 8; o >>= 1) {
                    #pragma unroll
                    for (int i = 0; i < 8; i++)
                        st[i] += __shfl_xor_sync(0xffffffffu, st[i], o);
                }
                #pragma unroll
                for (int o = 4; o >= 1; o >>= 1) {
                    #pragma unroll
                    for (int i = 0; i < o; i++) {
                        bool hi = (lane & o) != 0;
                        float mine   = hi ? st[i+o] : st[i];
                        float theirs = hi ? st[i]   : st[i+o];
                        st[i] = mine + __shfl_xor_sync(0xffffffffu, theirs, o);
                    }
                }

                const int r = lane >> 3, h = lane & 7;
                float sfin = st[0];
                float mean = __shfl_sync(0xffffffffu, sfin, r) * (1.f/NL);
                float sqv  = __shfl_sync(0xffffffffu, sfin, r + 4) * (1.f/NL);
                float rs   = rsqrtf(sqv - mean*mean + 1e-5f);
                float s = (rs * (dd[0] - mean * ugs_r) + ub_r) * 0.125f;
                sc_s[h*SCSTR + wid*4 + r] = s;
                if (h == 0) { mrow_s[wid*4 + r] = mean; rrow_s[wid*4 + r] = rs; }
            }
            BAR_PROD();          // sc/mrow/rrow ready

            // ---- phase 4: warp wid = head wid; softmax over 32 p ----
            {
                const int p = lane;
                float s = sc_s[wid*SCSTR + p];
                float tmax = s;
                #pragma unroll
                for (int o = 16; o > 0; o >>= 1)
                    tmax = fmaxf(tmax, __shfl_xor_sync(~0u, tmax, o));
                float mn = fmaxf(mr, tmax);
                float e  = __expf(s - mn);
                float ea = e * rrow_s[p];
                float z = e, tt = ea * mrow_s[p];
                #pragma unroll
                for (int o = 16; o > 0; o >>= 1) {
                    z  += __shfl_xor_sync(~0u, z,  o);
                    tt += __shfl_xor_sync(~0u, tt, o);
                }
                float scale = __expf(mr - mn);
                zr = zr*scale + z;
                tr = tr*scale + tt;
                mr = mn;
                ea_s[(tile & 1)*NH*TILE + wid*TILE + p] = ea;
                if (lane == 0) scale_s[(tile & 1)*NH + wid] = scale;
                g_scores[((size_t)(b*NH + wid))*NP + split*ROWS_PER_BLK + tile*TILE + p] = s;
            }
            BAR_ARRIVE512(4 + (tile & 1));   // signal full

            st_cur = st_nxt;
            st_nxt = (st_nxt + 1 == NSTG) ? 0 : st_nxt + 1;
        }

        if (lane == 0) {
            int idx = (b*SPLIT + split)*NH + wid;
            g_pm[idx] = mr;
            g_pz[idx] = zr;
            g_pt[idx] = tr;
        }
    } else {
        // =================== CONSUMER (warps 8-15), pg-split ===================
        const int tc = t - 256;            // 0..255
        const int cg = tc & 127;           // 16B column group
        const int pg = tc >> 7;            // p half: [pg*16, pg*16+16)
        ulonglong2 A2[8];                  // A2[h] = 4 cols for head h
        #pragma unroll
        for (int j = 0; j < 8; j++) { A2[j].x = 0ull; A2[j].y = 0ull; }

        int st_cur = 0;
        #pragma unroll 1
        for (int tile = 0; tile < NTILES; tile++) {
            BAR_SYNC512(4 + (tile & 1));   // wait full

            const float* eab = ea_s + (tile & 1)*NH*TILE;
            #pragma unroll
            for (int j = 0; j < 8; j++) {
                float sj = scale_s[(tile & 1)*NH + j];
                unsigned long long sj2 = pack2(sj, sj);
                A2[j].x = mul2(A2[j].x, sj2);
                A2[j].y = mul2(A2[j].y, sj2);
            }
            const ulonglong2* xc2 = (const ulonglong2*)(buf + st_cur*TILE*NL);
            #pragma unroll
            for (int pq = 0; pq < 4; pq++) {
                const int p0 = pg*16 + pq*4;
                ulonglong2 v0 = xc2[(p0+0)*128 + cg];
                ulonglong2 v1 = xc2[(p0+1)*128 + cg];
                ulonglong2 v2 = xc2[(p0+2)*128 + cg];
                ulonglong2 v3 = xc2[(p0+3)*128 + cg];
                #pragma unroll
                for (int j = 0; j < 8; j++) {
                    float4 e = *(const float4*)&eab[j*TILE + p0];
                    unsigned long long q0 = pack2(e.x, e.x);
                    unsigned long long q1 = pack2(e.y, e.y);
                    unsigned long long q2_ = pack2(e.z, e.z);
                    unsigned long long q3 = pack2(e.w, e.w);
                    A2[j].x = fma2(q0, v0.x, A2[j].x);  A2[j].y = fma2(q0, v0.y, A2[j].y);
                    A2[j].x = fma2(q1, v1.x, A2[j].x);  A2[j].y = fma2(q1, v1.y, A2[j].y);
                    A2[j].x = fma2(q2_, v2.x, A2[j].x); A2[j].y = fma2(q2_, v2.y, A2[j].y);
                    A2[j].x = fma2(q3, v3.x, A2[j].x);  A2[j].y = fma2(q3, v3.y, A2[j].y);
                }
            }
            BAR_ARRIVE512(2 + (tile & 1));   // signal free

            st_cur = (st_cur + 1 == NSTG) ? 0 : st_cur + 1;
        }

        // epilogue: combine the two p-halves via the (now idle) staging buffer
        BAR_CONS();                          // all consumers done reading buf
        if (pg == 1) {
            float4* tmp = (float4*)buf;
            #pragma unroll
            for (int j = 0; j < 8; j++) tmp[j*128 + cg] = *(float4*)&A2[j];
        }
        BAR_CONS();
        if (pg == 0) {
            const float4* tmp = (const float4*)buf;
            float4* pa = (float4*)(g_pa + (size_t)(b*SPLIT + split)*NH*NL);
            #pragma unroll
            for (int j = 0; j < 8; j++) {
                float4 o = tmp[j*128 + cg];
                float4 a = *(float4*)&A2[j];
                o.x += a.x; o.y += a.y; o.z += a.z; o.w += a.w;
                pa[j*128 + cg] = o;
            }
        }
    }
}

// =========================================================================
// Kernel 3 (512 threads, latency-hidden): combine split partials per (b,h);
//   project through W_v; out = residual + ctx; normalized attn row.
//   Attn-phase score loads issued FIRST to hide under combine + GEMV.
// =========================================================================
__global__ void __launch_bounds__(512) k3_combine(
    const float* __restrict__ W_v,
    const float* __restrict__ lnkv_g, const float* __restrict__ lnkv_b,
    float* __restrict__ out)
{
    __shared__ float es[SPLIT];
    __shared__ float sT, sInvZ, sM;
    __shared__ float cvec[NL];
    __shared__ float part[8*64];

    const int t = threadIdx.x;
    const int b = blockIdx.x >> 3, h = blockIdx.x & 7;

    // issue the attn-phase score load immediately (independent of everything)
    const float4* sc4 = (const float4*)(g_scores + ((size_t)(b*NH + h))*NP);
    float4 sreg = sc4[t];                          // 512 x float4 = 2048 scores

    if (t == 0) {
        float M = NEG_INF;
        #pragma unroll
        for (int i = 0; i < SPLIT; i++)
            M = fmaxf(M, g_pm[(b*SPLIT + i)*NH + h]);
        float Z = 0.f, T = 0.f;
        #pragma unroll
        for (int i = 0; i < SPLIT; i++) {
            int idx = (b*SPLIT + i)*NH + h;
            float e = __expf(g_pm[idx] - M);
            es[i] = e;
            Z += g_pz[idx] * e;
            T += g_pt[idx] * e;
        }
        float iz = 1.f / Z;
        sT = T; sInvZ = iz; sM = M;
    }
    __syncthreads();

    // combine split partials: one l per thread
    {
        const float* pa = g_pa + ((size_t)(b*SPLIT)*NH + h)*NL;
        float A = pa[t] * es[0] + pa[NH*NL + t] * es[1];
        cvec[t] = lnkv_g[t] * (A - sT) * sInvZ + lnkv_b[t];
    }
    __syncthreads();

    // W_v projection: 8 l-groups x 64 d
    {
        const int d = t & 63, lg = t >> 6;
        float acc = 0.f;
        const int l0 = lg * 64;
        #pragma unroll 8
        for (int l = l0; l < l0 + 64; l++)
            acc += cvec[l] * W_v[l*NDM + h*NDK + d];
        part[lg*64 + d] = acc;
    }
    __syncthreads();
    if (t < 64) {
        float c = 0.f;
        #pragma unroll
        for (int g = 0; g < 8; g++) c += part[g*64 + t];
        out[b*NDM + h*NDK + t] = c + g_res[b*NDM + h*NDK + t];
    }

    // attn output row for this (b,h): exp(score - M) * invZ  (score preloaded)
    {
        const float M = sM, iz = sInvZ;
        float4 o;
        o.x = __expf(sreg.x - M) * iz;
        o.y = __expf(sreg.y - M) * iz;
        o.z = __expf(sreg.z - M) * iz;
        o.w = __expf(sreg.w - M) * iz;
        ((float4*)(out + NB*NDM + ((size_t)(b*NH + h))*NP))[t] = o;
    }
}

// =========================================================================
extern "C" void kernel_launch(void* const* d_in, const int* in_sizes, int n_in,
                              void* d_out, int out_size)
{
    const float* x_trafic  = (const float*)d_in[0];
    const float* x_dynamic = (const float*)d_in[1];
    // d_in[2] x_known unused by the reference
    const float* W_q    = (const float*)d_in[3];
    const float* W_k    = (const float*)d_in[4];
    const float* W_v    = (const float*)d_in[5];
    const float* lnq_g  = (const float*)d_in[6];
    const float* lnq_b  = (const float*)d_in[7];
    const float* lnkv_g = (const float*)d_in[8];
    const float* lnkv_b = (const float*)d_in[9];
    const float* res_W  = (const float*)d_in[10];
    const float* res_b  = (const float*)d_in[11];
    float* out = (float*)d_out;

    const int smem1b = (128*65 + 128*8) * (int)sizeof(float4);   // ~149.5 KB
    const int smem2  = (NSTG*TILE*NL + NH*NL + NH*SCSTR + 2*NH*TILE + 16 + 2*TILE)
                       * (int)sizeof(float);                     // ~211.4 KB
    cudaFuncSetAttribute(k1b_gemm, cudaFuncAttributeMaxDynamicSharedMemorySize, smem1b);
    cudaFuncSetAttribute(k2_main,  cudaFuncAttributeMaxDynamicSharedMemorySize, smem2);

    k1b_gemm<<<128, 512, smem1b>>>(x_trafic, W_q, res_W, res_b, lnq_g, lnq_b);
    k1c_u<<<128, 512>>>(W_k, lnkv_g, lnkv_b);
    k2_main<<<dim3(SPLIT, NB), 512, smem2>>>(x_dynamic);
    k3_combine<<<NB*NH, 512>>>(W_v, lnkv_g, lnkv_b, out);
}